// round 4
// baseline (speedup 1.0000x reference)
#include <cuda_runtime.h>
#include <math.h>

#define B_ 8
#define T_ 2048
#define C_ 1024
#define H_ 64
#define NROWS (B_ * T_)   // 16384

__device__ float g_q[NROWS * H_];
__device__ float g_k[NROWS * H_];
__device__ float g_v[NROWS * H_];
__device__ float g_res[NROWS * H_];
__device__ float g_rowsum[NROWS];
__device__ float g_attn_scratch[(size_t)B_ * T_ * T_];

typedef unsigned long long ull;

__device__ __forceinline__ ull pack_dup(float x) {
    ull r; unsigned u = __float_as_uint(x);
    asm("mov.b64 %0, {%1, %1};" : "=l"(r) : "r"(u));
    return r;
}
__device__ __forceinline__ void ffma2(ull& acc, ull a, ull b) {
    asm("fma.rn.f32x2 %0, %1, %2, %3;" : "=l"(acc) : "l"(a), "l"(b), "l"(acc));
}
__device__ __forceinline__ float2 unpack2(ull v) {
    unsigned lo, hi;
    asm("mov.b64 {%0, %1}, %2;" : "=r"(lo), "=r"(hi) : "l"(v));
    return make_float2(__uint_as_float(lo), __uint_as_float(hi));
}

// ---------------------------------------------------------------------------
// Kernel 1: fused QKV projection. grid=256, block=256. Tile 64m x (3x64)h.
// Per thread 4m x (4h per W x 3W). x read ONCE (64MB instead of 192MB).
// smem: Xs[64m][68] + Ws[3][64kk][64h].
// ---------------------------------------------------------------------------
#define PROJ_SMEM (64 * 68 * 4 + 3 * 64 * 64 * 4)
__global__ __launch_bounds__(256, 3) void proj_kernel(const float* __restrict__ x,
                                                      const float* __restrict__ Wq,
                                                      const float* __restrict__ Wk,
                                                      const float* __restrict__ Wv) {
    extern __shared__ float sm[];
    float* Xs = sm;            // [64][68]
    float* Ws = sm + 64 * 68;  // [3][64][64]

    const int row0 = blockIdx.x * 64;
    const int tid = threadIdx.x;
    const int tx = tid & 15;   // 16 h-quads
    const int ty = tid >> 4;   // 16 m-groups of 4

    ull acc[4][6] = {};

    for (int k0 = 0; k0 < C_; k0 += 64) {
        #pragma unroll
        for (int it = 0; it < 4; it++) {
            int idx = tid + it * 256;          // 1024 quads = 64 x 16
            int r = idx >> 4, c4 = idx & 15;
            *(float4*)&Xs[r * 68 + c4 * 4] =
                *(const float4*)&x[(size_t)(row0 + r) * C_ + k0 + c4 * 4];
        }
        #pragma unroll
        for (int it = 0; it < 4; it++) {
            int idx = tid + it * 256;
            int r = idx >> 4, c4 = idx & 15;
            size_t g = (size_t)(k0 + r) * H_ + c4 * 4;
            *(float4*)&Ws[r * 64 + c4 * 4]            = *(const float4*)&Wq[g];
            *(float4*)&Ws[4096 + r * 64 + c4 * 4]     = *(const float4*)&Wk[g];
            *(float4*)&Ws[8192 + r * 64 + c4 * 4]     = *(const float4*)&Wv[g];
        }
        __syncthreads();

        #pragma unroll 4
        for (int kk = 0; kk < 64; kk++) {
            ull am[4];
            #pragma unroll
            for (int j = 0; j < 4; j++) am[j] = pack_dup(Xs[(ty * 4 + j) * 68 + kk]);
            ulonglong2 bq = *(const ulonglong2*)&Ws[kk * 64 + tx * 4];
            ulonglong2 bk = *(const ulonglong2*)&Ws[4096 + kk * 64 + tx * 4];
            ulonglong2 bv = *(const ulonglong2*)&Ws[8192 + kk * 64 + tx * 4];
            #pragma unroll
            for (int j = 0; j < 4; j++) {
                ffma2(acc[j][0], am[j], bq.x); ffma2(acc[j][1], am[j], bq.y);
                ffma2(acc[j][2], am[j], bk.x); ffma2(acc[j][3], am[j], bk.y);
                ffma2(acc[j][4], am[j], bv.x); ffma2(acc[j][5], am[j], bv.y);
            }
        }
        __syncthreads();
    }

    #pragma unroll
    for (int j = 0; j < 4; j++) {
        size_t off = (size_t)(row0 + ty * 4 + j) * H_ + tx * 4;
        float2 a, b;
        a = unpack2(acc[j][0]); b = unpack2(acc[j][1]);
        *(float4*)&g_q[off] = make_float4(a.x, a.y, b.x, b.y);
        a = unpack2(acc[j][2]); b = unpack2(acc[j][3]);
        *(float4*)&g_k[off] = make_float4(a.x, a.y, b.x, b.y);
        a = unpack2(acc[j][4]); b = unpack2(acc[j][5]);
        *(float4*)&g_v[off] = make_float4(a.x, a.y, b.x, b.y);
    }
}

// ---------------------------------------------------------------------------
// Kernel 2: E = exp(Q@K^T / 32) lower tiles, zeros upper; row-sum atomics.
// grid=(16 s,32 t,8 b), block=128. Tile 64t x 128s, per thread 8t x 8s.
// ---------------------------------------------------------------------------
#define SCORES_SMEM (64 * 68 * 4 + 64 * 132 * 4)
__global__ __launch_bounds__(128, 4) void scores_kernel(float* __restrict__ attn) {
    const int s_t = blockIdx.x, t_t = blockIdx.y;
    const int b = blockIdx.z;
    const int t0 = t_t * 64, s0 = s_t * 128;
    const int tid = threadIdx.x;

    if (s0 > t0 + 63) {  // strictly-upper tile: zero fill
        #pragma unroll
        for (int it = 0; it < 16; it++) {
            int idx = tid + it * 128;       // 2048 quads = 64 x 32
            int r = idx >> 5, c4 = idx & 31;
            *(float4*)&attn[((size_t)b * T_ + t0 + r) * T_ + s0 + c4 * 4] =
                make_float4(0.f, 0.f, 0.f, 0.f);
        }
        return;
    }

    extern __shared__ float sm[];
    float* Qs_T = sm;            // [64 h][68 t]
    float* Ks_T = sm + 64 * 68;  // [64 h][132 s]

    const float* q = g_q + (size_t)b * T_ * H_;
    const float* k = g_k + (size_t)b * T_ * H_;

    const int lh = tid & 63;
    const int lg = tid >> 6;  // 0..1
    #pragma unroll
    for (int it = 0; it < 8; it++) {
        int t4 = (it * 2 + lg) * 4;
        const float* qp = &q[(size_t)(t0 + t4) * H_ + lh];
        *(float4*)&Qs_T[lh * 68 + t4] =
            make_float4(qp[0], qp[H_], qp[2 * H_], qp[3 * H_]);
    }
    #pragma unroll
    for (int it = 0; it < 16; it++) {
        int s4 = (it * 2 + lg) * 4;
        const float* kp = &k[(size_t)(s0 + s4) * H_ + lh];
        *(float4*)&Ks_T[lh * 132 + s4] =
            make_float4(kp[0], kp[H_], kp[2 * H_], kp[3 * H_]);
    }
    __syncthreads();

    const int tx = tid & 15;  // 16 s-groups of 8
    const int ty = tid >> 4;  // 8 t-groups of 8

    ull acc[8][4] = {};
    #pragma unroll 2
    for (int kk = 0; kk < 64; kk++) {
        float4 a0 = *(const float4*)&Qs_T[kk * 68 + ty * 8];
        float4 a1 = *(const float4*)&Qs_T[kk * 68 + ty * 8 + 4];
        ull am[8];
        am[0] = pack_dup(a0.x); am[1] = pack_dup(a0.y);
        am[2] = pack_dup(a0.z); am[3] = pack_dup(a0.w);
        am[4] = pack_dup(a1.x); am[5] = pack_dup(a1.y);
        am[6] = pack_dup(a1.z); am[7] = pack_dup(a1.w);
        ulonglong2 b01 = *(const ulonglong2*)&Ks_T[kk * 132 + tx * 8];
        ulonglong2 b23 = *(const ulonglong2*)&Ks_T[kk * 132 + tx * 8 + 4];
        ull bp[4] = {b01.x, b01.y, b23.x, b23.y};
        #pragma unroll
        for (int i = 0; i < 8; i++)
            #pragma unroll
            for (int p = 0; p < 4; p++) ffma2(acc[i][p], am[i], bp[p]);
    }

    const float sc = 0.03125f;  // 1/sqrt(1024)
    const bool need_mask = (s0 + 127 > t0);
    #pragma unroll
    for (int i = 0; i < 8; i++) {
        const int tglob = t0 + ty * 8 + i;
        const size_t row = (size_t)b * T_ + tglob;
        float e[8];
        #pragma unroll
        for (int p = 0; p < 4; p++) {
            float2 f = unpack2(acc[i][p]);
            int sg = s0 + tx * 8 + p * 2;
            e[p * 2]     = (!need_mask || sg     <= tglob) ? __expf(f.x * sc) : 0.f;
            e[p * 2 + 1] = (!need_mask || sg + 1 <= tglob) ? __expf(f.y * sc) : 0.f;
        }
        float rs = ((e[0] + e[1]) + (e[2] + e[3])) + ((e[4] + e[5]) + (e[6] + e[7]));
        #pragma unroll
        for (int off = 8; off; off >>= 1) rs += __shfl_xor_sync(0xffffffffu, rs, off);
        if (tx == 0) atomicAdd(&g_rowsum[row], rs);
        *(float4*)&attn[row * T_ + s0 + tx * 8]     = make_float4(e[0], e[1], e[2], e[3]);
        *(float4*)&attn[row * T_ + s0 + tx * 8 + 4] = make_float4(e[4], e[5], e[6], e[7]);
    }
}

// ---------------------------------------------------------------------------
// Kernel 3: av + fused normalization. grid=(32 t-tiles desc, 8 b), block=128.
// Tile 64t x 64h, per thread 4t x 8h, loops over s-chunks of 64 up to diag.
// Loader scales E by 1/rowsum, writes normalized attn back to gmem, and feeds
// the MMA. res written once per element (no atomics).
// ---------------------------------------------------------------------------
#define AV_SMEM (64 * 68 * 4 + 64 * 64 * 4 + 64 * 4)
__global__ __launch_bounds__(128, 6) void av_kernel(float* __restrict__ attn,
                                                    float* __restrict__ res) {
    const int t_t = 31 - blockIdx.x;   // big tiles first
    const int b = blockIdx.y;
    const int t0 = t_t * 64;
    const int tid = threadIdx.x;

    extern __shared__ float sm[];
    float* As   = sm;                    // [64 t][68 s]
    float* Vs   = sm + 64 * 68;          // [64 s][64 h]
    float* sinv = sm + 64 * 68 + 64 * 64;

    if (tid < 64) sinv[tid] = 1.f / g_rowsum[(size_t)b * T_ + t0 + tid];
    __syncthreads();

    const float* v = g_v + (size_t)b * T_ * H_;
    const int tx = tid & 7;   // 8 h-groups of 8
    const int ty = tid >> 3;  // 16 t-groups of 4

    ull acc[4][4] = {};

    for (int c = 0; c <= t_t; c++) {
        const int s0 = c * 64;
        #pragma unroll
        for (int it = 0; it < 8; it++) {
            int idx = tid + it * 128;       // 1024 quads = 64 x 16
            int r = idx >> 4, c4 = idx & 15;
            float* ap = &attn[((size_t)b * T_ + t0 + r) * T_ + s0 + c4 * 4];
            float4 f = *(const float4*)ap;
            float iv = sinv[r];
            f = make_float4(f.x * iv, f.y * iv, f.z * iv, f.w * iv);
            *(float4*)ap = f;               // normalized attn back to gmem
            *(float4*)&As[r * 68 + c4 * 4] = f;
        }
        #pragma unroll
        for (int it = 0; it < 8; it++) {
            int idx = tid + it * 128;
            int r = idx >> 4, c4 = idx & 15;
            *(float4*)&Vs[r * 64 + c4 * 4] =
                *(const float4*)&v[(size_t)(s0 + r) * H_ + c4 * 4];
        }
        __syncthreads();

        #pragma unroll 4
        for (int kk = 0; kk < 64; kk++) {
            ull am[4];
            #pragma unroll
            for (int j = 0; j < 4; j++) am[j] = pack_dup(As[(ty * 4 + j) * 68 + kk]);
            ulonglong2 b01 = *(const ulonglong2*)&Vs[kk * 64 + tx * 8];
            ulonglong2 b23 = *(const ulonglong2*)&Vs[kk * 64 + tx * 8 + 4];
            ull bp[4] = {b01.x, b01.y, b23.x, b23.y};
            #pragma unroll
            for (int j = 0; j < 4; j++)
                #pragma unroll
                for (int p = 0; p < 4; p++) ffma2(acc[j][p], am[j], bp[p]);
        }
        __syncthreads();
    }

    #pragma unroll
    for (int j = 0; j < 4; j++) {
        size_t row = (size_t)b * T_ + t0 + ty * 4 + j;
        float2 p0 = unpack2(acc[j][0]), p1 = unpack2(acc[j][1]);
        float2 p2 = unpack2(acc[j][2]), p3 = unpack2(acc[j][3]);
        *(float4*)&res[row * H_ + tx * 8]     = make_float4(p0.x, p0.y, p1.x, p1.y);
        *(float4*)&res[row * H_ + tx * 8 + 4] = make_float4(p2.x, p2.y, p3.x, p3.y);
    }
}

// ---------------------------------------------------------------------------
extern "C" void kernel_launch(void* const* d_in, const int* in_sizes, int n_in,
                              void* d_out, int out_size) {
    (void)in_sizes; (void)n_in;
    const float* x  = (const float*)d_in[0];
    const float* Wq = (const float*)d_in[1];
    const float* Wk = (const float*)d_in[2];
    const float* Wv = (const float*)d_in[3];

    const size_t n_res  = (size_t)B_ * T_ * H_;
    const size_t n_attn = (size_t)B_ * T_ * T_;

    float* attn_scratch = nullptr;
    float* res_scratch = nullptr;
    float* rowsum = nullptr;
    cudaGetSymbolAddress((void**)&attn_scratch, g_attn_scratch);
    cudaGetSymbolAddress((void**)&res_scratch, g_res);
    cudaGetSymbolAddress((void**)&rowsum, g_rowsum);

    float* res;
    float* attn;
    if ((size_t)out_size == n_res + n_attn) {
        res  = (float*)d_out;
        attn = (float*)d_out + n_res;
    } else if ((size_t)out_size == n_attn) {
        attn = (float*)d_out;
        res  = res_scratch;
    } else {
        res  = (float*)d_out;
        attn = attn_scratch;
    }

    cudaFuncSetAttribute(proj_kernel,   cudaFuncAttributeMaxDynamicSharedMemorySize, PROJ_SMEM);
    cudaFuncSetAttribute(scores_kernel, cudaFuncAttributeMaxDynamicSharedMemorySize, SCORES_SMEM);
    cudaFuncSetAttribute(av_kernel,     cudaFuncAttributeMaxDynamicSharedMemorySize, AV_SMEM);

    cudaMemsetAsync(rowsum, 0, NROWS * sizeof(float));
    proj_kernel<<<256, 256, PROJ_SMEM>>>(x, Wq, Wk, Wv);
    scores_kernel<<<dim3(16, 32, 8), 128, SCORES_SMEM>>>(attn);
    av_kernel<<<dim3(32, 8), 128, AV_SMEM>>>(attn, res);
}

// round 5
// speedup vs baseline: 1.3335x; 1.3335x over previous
#include <cuda_runtime.h>
#include <math.h>

#define B_ 8
#define T_ 2048
#define C_ 1024
#define H_ 64
#define NROWS (B_ * T_)   // 16384

__device__ float g_q[NROWS * H_];
__device__ float g_k[NROWS * H_];
__device__ float g_v[NROWS * H_];
__device__ float g_res[NROWS * H_];
__device__ float g_rowsum[NROWS];
__device__ float g_attn_scratch[(size_t)B_ * T_ * T_];

typedef unsigned long long ull;

__device__ __forceinline__ ull pack_dup(float x) {
    ull r; unsigned u = __float_as_uint(x);
    asm("mov.b64 %0, {%1, %1};" : "=l"(r) : "r"(u));
    return r;
}
__device__ __forceinline__ void ffma2(ull& acc, ull a, ull b) {
    asm("fma.rn.f32x2 %0, %1, %2, %3;" : "=l"(acc) : "l"(a), "l"(b), "l"(acc));
}
__device__ __forceinline__ float2 unpack2(ull v) {
    unsigned lo, hi;
    asm("mov.b64 {%0, %1}, %2;" : "=r"(lo), "=r"(hi) : "l"(v));
    return make_float2(__uint_as_float(lo), __uint_as_float(hi));
}

// ---------------------------------------------------------------------------
// Kernel 1: QKV projection (split). grid=(128, 3), block=256.
// Tile 128m x 64h, K-chunk 64, per thread 4m x 8h.
// Xs_T is kk-major so the A-side is one LDS.128 per kk.
// ---------------------------------------------------------------------------
#define XT_P 132
#define PROJ_SMEM (64 * XT_P * 4 + 64 * 64 * 4)   // 50176 B
__global__ __launch_bounds__(256, 3) void proj_kernel(const float* __restrict__ x,
                                                      const float* __restrict__ Wq,
                                                      const float* __restrict__ Wk,
                                                      const float* __restrict__ Wv) {
    extern __shared__ float sm[];
    float* Xs_T = sm;              // [64 kk][132 m]
    float* Ws   = sm + 64 * XT_P;  // [64 kk][64 h]

    const float* W; float* out;
    if (blockIdx.y == 0)      { W = Wq; out = g_q; }
    else if (blockIdx.y == 1) { W = Wk; out = g_k; }
    else                      { W = Wv; out = g_v; }

    const int row0 = blockIdx.x * 128;
    const int tid = threadIdx.x;
    const int tx = tid & 7;    // 8 h-groups of 8
    const int ty = tid >> 3;   // 32 m-groups of 4

    const int lc = tid & 63;   // kk within chunk
    const int lg = tid >> 6;   // 0..3

    ull acc[4][4] = {};

    for (int k0 = 0; k0 < C_; k0 += 64) {
        #pragma unroll
        for (int it = 0; it < 8; it++) {
            int m4 = (it * 4 + lg) * 4;
            const float* xp = &x[(size_t)(row0 + m4) * C_ + k0 + lc];
            *(float4*)&Xs_T[lc * XT_P + m4] =
                make_float4(xp[0], xp[C_], xp[2 * C_], xp[3 * C_]);
        }
        #pragma unroll
        for (int it = 0; it < 4; it++) {
            int idx = tid + it * 256;          // 1024 quads = 64 x 16
            int r = idx >> 4, c4 = idx & 15;
            *(float4*)&Ws[r * 64 + c4 * 4] =
                *(const float4*)&W[(size_t)(k0 + r) * H_ + c4 * 4];
        }
        __syncthreads();

        #pragma unroll 4
        for (int kk = 0; kk < 64; kk++) {
            float4 a = *(const float4*)&Xs_T[kk * XT_P + ty * 4];
            ull am[4] = {pack_dup(a.x), pack_dup(a.y), pack_dup(a.z), pack_dup(a.w)};
            ulonglong2 b01 = *(const ulonglong2*)&Ws[kk * 64 + tx * 8];
            ulonglong2 b23 = *(const ulonglong2*)&Ws[kk * 64 + tx * 8 + 4];
            ull bp[4] = {b01.x, b01.y, b23.x, b23.y};
            #pragma unroll
            for (int j = 0; j < 4; j++)
                #pragma unroll
                for (int p = 0; p < 4; p++) ffma2(acc[j][p], am[j], bp[p]);
        }
        __syncthreads();
    }

    #pragma unroll
    for (int j = 0; j < 4; j++) {
        size_t row = (size_t)(row0 + ty * 4 + j);
        float2 p0 = unpack2(acc[j][0]), p1 = unpack2(acc[j][1]);
        float2 p2 = unpack2(acc[j][2]), p3 = unpack2(acc[j][3]);
        *(float4*)&out[row * H_ + tx * 8]     = make_float4(p0.x, p0.y, p1.x, p1.y);
        *(float4*)&out[row * H_ + tx * 8 + 4] = make_float4(p2.x, p2.y, p3.x, p3.y);
    }
}

// ---------------------------------------------------------------------------
// Kernel 2: E = exp(Q@K^T / 32) lower tiles, zeros upper; row-sum atomics.
// grid=(16 s,32 t,8 b), block=128. Tile 64t x 128s, per thread 8t x 8s.
// (unchanged from round 3)
// ---------------------------------------------------------------------------
#define SCORES_SMEM (64 * 68 * 4 + 64 * 132 * 4)
__global__ __launch_bounds__(128, 4) void scores_kernel(float* __restrict__ attn) {
    const int s_t = blockIdx.x, t_t = blockIdx.y;
    const int b = blockIdx.z;
    const int t0 = t_t * 64, s0 = s_t * 128;
    const int tid = threadIdx.x;

    if (s0 > t0 + 63) {  // strictly-upper tile: zero fill
        #pragma unroll
        for (int it = 0; it < 16; it++) {
            int idx = tid + it * 128;       // 2048 quads = 64 x 32
            int r = idx >> 5, c4 = idx & 31;
            *(float4*)&attn[((size_t)b * T_ + t0 + r) * T_ + s0 + c4 * 4] =
                make_float4(0.f, 0.f, 0.f, 0.f);
        }
        return;
    }

    extern __shared__ float sm[];
    float* Qs_T = sm;            // [64 h][68 t]
    float* Ks_T = sm + 64 * 68;  // [64 h][132 s]

    const float* q = g_q + (size_t)b * T_ * H_;
    const float* k = g_k + (size_t)b * T_ * H_;

    const int lh = tid & 63;
    const int lg = tid >> 6;  // 0..1
    #pragma unroll
    for (int it = 0; it < 8; it++) {
        int t4 = (it * 2 + lg) * 4;
        const float* qp = &q[(size_t)(t0 + t4) * H_ + lh];
        *(float4*)&Qs_T[lh * 68 + t4] =
            make_float4(qp[0], qp[H_], qp[2 * H_], qp[3 * H_]);
    }
    #pragma unroll
    for (int it = 0; it < 16; it++) {
        int s4 = (it * 2 + lg) * 4;
        const float* kp = &k[(size_t)(s0 + s4) * H_ + lh];
        *(float4*)&Ks_T[lh * 132 + s4] =
            make_float4(kp[0], kp[H_], kp[2 * H_], kp[3 * H_]);
    }
    __syncthreads();

    const int tx = tid & 15;  // 16 s-groups of 8
    const int ty = tid >> 4;  // 8 t-groups of 8

    ull acc[8][4] = {};
    #pragma unroll 2
    for (int kk = 0; kk < 64; kk++) {
        float4 a0 = *(const float4*)&Qs_T[kk * 68 + ty * 8];
        float4 a1 = *(const float4*)&Qs_T[kk * 68 + ty * 8 + 4];
        ull am[8];
        am[0] = pack_dup(a0.x); am[1] = pack_dup(a0.y);
        am[2] = pack_dup(a0.z); am[3] = pack_dup(a0.w);
        am[4] = pack_dup(a1.x); am[5] = pack_dup(a1.y);
        am[6] = pack_dup(a1.z); am[7] = pack_dup(a1.w);
        ulonglong2 b01 = *(const ulonglong2*)&Ks_T[kk * 132 + tx * 8];
        ulonglong2 b23 = *(const ulonglong2*)&Ks_T[kk * 132 + tx * 8 + 4];
        ull bp[4] = {b01.x, b01.y, b23.x, b23.y};
        #pragma unroll
        for (int i = 0; i < 8; i++)
            #pragma unroll
            for (int p = 0; p < 4; p++) ffma2(acc[i][p], am[i], bp[p]);
    }

    const float sc = 0.03125f;  // 1/sqrt(1024)
    const bool need_mask = (s0 + 127 > t0);
    #pragma unroll
    for (int i = 0; i < 8; i++) {
        const int tglob = t0 + ty * 8 + i;
        const size_t row = (size_t)b * T_ + tglob;
        float e[8];
        #pragma unroll
        for (int p = 0; p < 4; p++) {
            float2 f = unpack2(acc[i][p]);
            int sg = s0 + tx * 8 + p * 2;
            e[p * 2]     = (!need_mask || sg     <= tglob) ? __expf(f.x * sc) : 0.f;
            e[p * 2 + 1] = (!need_mask || sg + 1 <= tglob) ? __expf(f.y * sc) : 0.f;
        }
        float rs = ((e[0] + e[1]) + (e[2] + e[3])) + ((e[4] + e[5]) + (e[6] + e[7]));
        #pragma unroll
        for (int off = 8; off; off >>= 1) rs += __shfl_xor_sync(0xffffffffu, rs, off);
        if (tx == 0) atomicAdd(&g_rowsum[row], rs);
        *(float4*)&attn[row * T_ + s0 + tx * 8]     = make_float4(e[0], e[1], e[2], e[3]);
        *(float4*)&attn[row * T_ + s0 + tx * 8 + 4] = make_float4(e[4], e[5], e[6], e[7]);
    }
}

// ---------------------------------------------------------------------------
// Kernel 3: normalize lower-triangular part of each row by 1/rowsum.
// ---------------------------------------------------------------------------
__global__ void normalize_kernel(float* __restrict__ attn) {
    const int row = blockIdx.x;
    const int t = row & (T_ - 1);
    const float inv = 1.f / g_rowsum[row];
    float4* p = (float4*)(attn + (size_t)row * T_);
    const int nq = (t >> 2) + 1;
    for (int i = threadIdx.x; i < nq; i += 256) {
        float4 v = p[i];
        p[i] = make_float4(v.x * inv, v.y * inv, v.z * inv, v.w * inv);
    }
}

// ---------------------------------------------------------------------------
// Kernel 4: res += attn @ V, split-K over 256-wide s-spans (4x64 inner).
// grid=(8 spans, 32 t-tiles desc, 8 b), block=128. Tile 64t x 64h.
// Per thread 4t x 8h. 34KB smem -> 6 CTAs/SM. Atomic lanes cut 4x.
// ---------------------------------------------------------------------------
#define AV_SMEM (64 * 68 * 4 + 64 * 64 * 4)   // 33792 B
__global__ __launch_bounds__(128, 6) void av_kernel(const float* __restrict__ attn,
                                                    float* __restrict__ res) {
    const int sc = blockIdx.x;
    const int t_t = 31 - blockIdx.y;   // big tiles first
    const int b = blockIdx.z;
    const int t0 = t_t * 64;
    if (sc * 256 > t0 + 63) return;

    extern __shared__ float sm[];
    float* As_T = sm;            // [64 s][68 t]
    float* Vs   = sm + 64 * 68;  // [64 s][64 h]

    const float* A = attn + (size_t)b * T_ * T_;
    const float* v = g_v + (size_t)b * T_ * H_;
    const int tid = threadIdx.x;
    const int tx = tid & 7;    // 8 h-groups of 8
    const int ty = tid >> 3;   // 16 t-groups of 4
    const int lc = tid & 63;   // s within chunk
    const int lg = tid >> 6;   // 0..1

    ull acc[4][4] = {};

    #pragma unroll
    for (int c2 = 0; c2 < 4; c2++) {
        const int s0 = sc * 256 + c2 * 64;
        if (s0 > t0 + 63) break;

        #pragma unroll
        for (int it = 0; it < 8; it++) {
            int t4 = (it * 2 + lg) * 4;
            const float* ap = &A[(size_t)(t0 + t4) * T_ + s0 + lc];
            *(float4*)&As_T[lc * 68 + t4] =
                make_float4(ap[0], ap[T_], ap[2 * T_], ap[3 * T_]);
        }
        #pragma unroll
        for (int it = 0; it < 8; it++) {
            int idx = tid + it * 128;       // 1024 quads = 64 x 16
            int r = idx >> 4, c4 = idx & 15;
            *(float4*)&Vs[r * 64 + c4 * 4] =
                *(const float4*)&v[(size_t)(s0 + r) * H_ + c4 * 4];
        }
        __syncthreads();

        #pragma unroll 4
        for (int kk = 0; kk < 64; kk++) {
            float4 a = *(const float4*)&As_T[kk * 68 + ty * 4];
            ull am[4] = {pack_dup(a.x), pack_dup(a.y), pack_dup(a.z), pack_dup(a.w)};
            ulonglong2 b01 = *(const ulonglong2*)&Vs[kk * 64 + tx * 8];
            ulonglong2 b23 = *(const ulonglong2*)&Vs[kk * 64 + tx * 8 + 4];
            ull bp[4] = {b01.x, b01.y, b23.x, b23.y};
            #pragma unroll
            for (int j = 0; j < 4; j++)
                #pragma unroll
                for (int p = 0; p < 4; p++) ffma2(acc[j][p], am[j], bp[p]);
        }
        __syncthreads();
    }

    #pragma unroll
    for (int j = 0; j < 4; j++) {
        size_t row = (size_t)b * T_ + t0 + ty * 4 + j;
        #pragma unroll
        for (int p = 0; p < 4; p++) {
            float2 f = unpack2(acc[j][p]);
            atomicAdd(&res[row * H_ + tx * 8 + p * 2],     f.x);
            atomicAdd(&res[row * H_ + tx * 8 + p * 2 + 1], f.y);
        }
    }
}

// ---------------------------------------------------------------------------
extern "C" void kernel_launch(void* const* d_in, const int* in_sizes, int n_in,
                              void* d_out, int out_size) {
    (void)in_sizes; (void)n_in;
    const float* x  = (const float*)d_in[0];
    const float* Wq = (const float*)d_in[1];
    const float* Wk = (const float*)d_in[2];
    const float* Wv = (const float*)d_in[3];

    const size_t n_res  = (size_t)B_ * T_ * H_;
    const size_t n_attn = (size_t)B_ * T_ * T_;

    float* attn_scratch = nullptr;
    float* res_scratch = nullptr;
    float* rowsum = nullptr;
    cudaGetSymbolAddress((void**)&attn_scratch, g_attn_scratch);
    cudaGetSymbolAddress((void**)&res_scratch, g_res);
    cudaGetSymbolAddress((void**)&rowsum, g_rowsum);

    float* res;
    float* attn;
    if ((size_t)out_size == n_res + n_attn) {
        res  = (float*)d_out;
        attn = (float*)d_out + n_res;
    } else if ((size_t)out_size == n_attn) {
        attn = (float*)d_out;
        res  = res_scratch;
    } else {
        res  = (float*)d_out;
        attn = attn_scratch;
    }

    cudaFuncSetAttribute(proj_kernel,   cudaFuncAttributeMaxDynamicSharedMemorySize, PROJ_SMEM);
    cudaFuncSetAttribute(scores_kernel, cudaFuncAttributeMaxDynamicSharedMemorySize, SCORES_SMEM);
    cudaFuncSetAttribute(av_kernel,     cudaFuncAttributeMaxDynamicSharedMemorySize, AV_SMEM);

    cudaMemsetAsync(rowsum, 0, NROWS * sizeof(float));
    cudaMemsetAsync(res, 0, n_res * sizeof(float));
    proj_kernel<<<dim3(128, 3), 256, PROJ_SMEM>>>(x, Wq, Wk, Wv);
    scores_kernel<<<dim3(16, 32, 8), 128, SCORES_SMEM>>>(attn);
    normalize_kernel<<<NROWS, 256>>>(attn);
    av_kernel<<<dim3(8, 32, 8), 128, AV_SMEM>>>(attn, res);
}

// round 6
// speedup vs baseline: 3.3043x; 2.4779x over previous
#include <cuda_runtime.h>
#include <math.h>

#define B_ 8
#define T_ 2048
#define C_ 1024
#define H_ 64
#define NROWS (B_ * T_)   // 16384

__device__ float g_q[NROWS * H_];
__device__ float g_k[NROWS * H_];
__device__ float g_v[NROWS * H_];
__device__ float g_res[NROWS * H_];
__device__ float g_rowsum[NROWS];
__device__ float g_attn_scratch[(size_t)B_ * T_ * T_];

// ---- tf32 helpers -----------------------------------------------------------
__device__ __forceinline__ unsigned tf32(float f) {
    unsigned r;
    asm("cvt.rna.tf32.f32 %0, %1;" : "=r"(r) : "f"(f));
    return r;
}
__device__ __forceinline__ uint4 tf32x4(float4 f) {
    uint4 u;
    u.x = tf32(f.x); u.y = tf32(f.y); u.z = tf32(f.z); u.w = tf32(f.w);
    return u;
}
// D += A(16x8,row) * B(8x8,col); tf32 in, fp32 accum
__device__ __forceinline__ void mma8(float* c, const unsigned* a, const unsigned* b) {
    asm("mma.sync.aligned.m16n8k8.row.col.f32.tf32.tf32.f32 "
        "{%0,%1,%2,%3},{%4,%5,%6,%7},{%8,%9},{%0,%1,%2,%3};"
        : "+f"(c[0]), "+f"(c[1]), "+f"(c[2]), "+f"(c[3])
        : "r"(a[0]), "r"(a[1]), "r"(a[2]), "r"(a[3]), "r"(b[0]), "r"(b[1]));
}

// ---------------------------------------------------------------------------
// Kernel 1: QKV projection. grid=(128, 3), block=256 (8 warps: 4m x 2n).
// Block tile 128m x 64h, K-chunk 64. Warp tile 32m x 32h.
// smem: Xs[128][68] tf32, Ws[64][72] tf32 (both natural row-major + pad).
// ---------------------------------------------------------------------------
#define PROJ_SMEM (128 * 68 * 4 + 64 * 72 * 4)   // 53248 B
__global__ __launch_bounds__(256, 3) void proj_kernel(const float* __restrict__ x,
                                                      const float* __restrict__ Wq,
                                                      const float* __restrict__ Wk,
                                                      const float* __restrict__ Wv) {
    extern __shared__ unsigned smu[];
    unsigned* Xs = smu;             // [128][68]
    unsigned* Ws = smu + 128 * 68;  // [64][72]

    const float* W; float* out;
    if (blockIdx.y == 0)      { W = Wq; out = g_q; }
    else if (blockIdx.y == 1) { W = Wk; out = g_k; }
    else                      { W = Wv; out = g_v; }

    const int row0 = blockIdx.x * 128;
    const int tid  = threadIdx.x;
    const int warp = tid >> 5;
    const int lane = tid & 31;
    const int g    = lane >> 2;    // groupID 0..7
    const int tig  = lane & 3;     // 0..3
    const int wm   = warp >> 1;    // 0..3 (m)
    const int wn   = warp & 1;     // 0..1 (n)

    float acc[2][4][4] = {};

    for (int k0 = 0; k0 < C_; k0 += 64) {
        #pragma unroll
        for (int it = 0; it < 8; it++) {
            int idx = tid + it * 256;         // 2048 float4 = 128 x 16
            int r = idx >> 4, c4 = idx & 15;
            *(uint4*)&Xs[r * 68 + c4 * 4] =
                tf32x4(*(const float4*)&x[(size_t)(row0 + r) * C_ + k0 + c4 * 4]);
        }
        #pragma unroll
        for (int it = 0; it < 4; it++) {
            int idx = tid + it * 256;         // 1024 float4 = 64 x 16
            int r = idx >> 4, c4 = idx & 15;
            *(uint4*)&Ws[r * 72 + c4 * 4] =
                tf32x4(*(const float4*)&W[(size_t)(k0 + r) * H_ + c4 * 4]);
        }
        __syncthreads();

        #pragma unroll
        for (int k8 = 0; k8 < 8; k8++) {
            const int kb = k8 * 8;
            unsigned a[2][4];
            #pragma unroll
            for (int mi = 0; mi < 2; mi++) {
                int m0 = wm * 32 + mi * 16;
                a[mi][0] = Xs[(m0 + g) * 68 + kb + tig];
                a[mi][1] = Xs[(m0 + g + 8) * 68 + kb + tig];
                a[mi][2] = Xs[(m0 + g) * 68 + kb + tig + 4];
                a[mi][3] = Xs[(m0 + g + 8) * 68 + kb + tig + 4];
            }
            #pragma unroll
            for (int nj = 0; nj < 4; nj++) {
                int n0 = wn * 32 + nj * 8;
                unsigned b[2];
                b[0] = Ws[(kb + tig) * 72 + n0 + g];
                b[1] = Ws[(kb + tig + 4) * 72 + n0 + g];
                #pragma unroll
                for (int mi = 0; mi < 2; mi++) mma8(acc[mi][nj], a[mi], b);
            }
        }
        __syncthreads();
    }

    #pragma unroll
    for (int mi = 0; mi < 2; mi++) {
        #pragma unroll
        for (int nj = 0; nj < 4; nj++) {
            int m0 = row0 + wm * 32 + mi * 16;
            int n0 = wn * 32 + nj * 8 + tig * 2;
            float* c = acc[mi][nj];
            *(float2*)&out[(size_t)(m0 + g) * H_ + n0]     = make_float2(c[0], c[1]);
            *(float2*)&out[(size_t)(m0 + g + 8) * H_ + n0] = make_float2(c[2], c[3]);
        }
    }
}

// ---------------------------------------------------------------------------
// Kernel 2: E = exp(Q@K^T / 32) lower tiles (zeros upper), rowsum atomics.
// grid=(16 s,32 t,8 b), block=128 (4 warps along s). Tile 64t x 128s.
// Warp tile 64t x 32s: m-frags 4, n-frags 4. K = 64 (8 k8-steps).
// smem: Qs[64][68] tf32, Ks[128][68] tf32, both natural row-major.
// ---------------------------------------------------------------------------
#define SCORES_SMEM (64 * 68 * 4 + 128 * 68 * 4)   // 52224 B
__global__ __launch_bounds__(128, 4) void scores_kernel(float* __restrict__ attn) {
    const int s_t = blockIdx.x, t_t = blockIdx.y;
    const int b = blockIdx.z;
    const int t0 = t_t * 64, s0 = s_t * 128;
    const int tid = threadIdx.x;

    if (s0 > t0 + 63) {  // strictly-upper tile: zero fill
        #pragma unroll
        for (int it = 0; it < 16; it++) {
            int idx = tid + it * 128;       // 2048 quads = 64 x 32
            int r = idx >> 5, c4 = idx & 31;
            *(float4*)&attn[((size_t)b * T_ + t0 + r) * T_ + s0 + c4 * 4] =
                make_float4(0.f, 0.f, 0.f, 0.f);
        }
        return;
    }

    extern __shared__ unsigned smu[];
    unsigned* Qs = smu;            // [64][68]
    unsigned* Ks = smu + 64 * 68;  // [128][68]

    const float* q = g_q + (size_t)b * T_ * H_;
    const float* k = g_k + (size_t)b * T_ * H_;

    #pragma unroll
    for (int it = 0; it < 8; it++) {
        int idx = tid + it * 128;          // 1024 float4 = 64 x 16
        int r = idx >> 4, c4 = idx & 15;
        *(uint4*)&Qs[r * 68 + c4 * 4] =
            tf32x4(*(const float4*)&q[(size_t)(t0 + r) * H_ + c4 * 4]);
    }
    #pragma unroll
    for (int it = 0; it < 16; it++) {
        int idx = tid + it * 128;          // 2048 float4 = 128 x 16
        int r = idx >> 4, c4 = idx & 15;
        *(uint4*)&Ks[r * 68 + c4 * 4] =
            tf32x4(*(const float4*)&k[(size_t)(s0 + r) * H_ + c4 * 4]);
    }
    __syncthreads();

    const int warp = tid >> 5;
    const int lane = tid & 31;
    const int g    = lane >> 2;
    const int tig  = lane & 3;

    float acc[4][4][4] = {};
    #pragma unroll
    for (int k8 = 0; k8 < 8; k8++) {
        const int kb = k8 * 8;
        unsigned a[4][4];
        #pragma unroll
        for (int mi = 0; mi < 4; mi++) {
            int m0 = mi * 16;
            a[mi][0] = Qs[(m0 + g) * 68 + kb + tig];
            a[mi][1] = Qs[(m0 + g + 8) * 68 + kb + tig];
            a[mi][2] = Qs[(m0 + g) * 68 + kb + tig + 4];
            a[mi][3] = Qs[(m0 + g + 8) * 68 + kb + tig + 4];
        }
        #pragma unroll
        for (int nj = 0; nj < 4; nj++) {
            int n0 = warp * 32 + nj * 8;
            unsigned bb[2];
            bb[0] = Ks[(n0 + g) * 68 + kb + tig];
            bb[1] = Ks[(n0 + g) * 68 + kb + tig + 4];
            // note: B fragment (k=tig(+4), n=g) -> Ks[s=n][h=k], s row-major
            #pragma unroll
            for (int mi = 0; mi < 4; mi++) mma8(acc[mi][nj], a[mi], bb);
        }
    }

    const float sc = 0.03125f;  // 1/sqrt(1024)
    const bool need_mask = (s0 + 127 > t0);
    #pragma unroll
    for (int mi = 0; mi < 4; mi++) {
        const int trow0 = t0 + mi * 16 + g;
        const int trow1 = trow0 + 8;
        float rs0 = 0.f, rs1 = 0.f;
        #pragma unroll
        for (int nj = 0; nj < 4; nj++) {
            int col = s0 + warp * 32 + nj * 8 + tig * 2;
            float* c = acc[mi][nj];
            float e0 = (!need_mask || col     <= trow0) ? __expf(c[0] * sc) : 0.f;
            float e1 = (!need_mask || col + 1 <= trow0) ? __expf(c[1] * sc) : 0.f;
            float e2 = (!need_mask || col     <= trow1) ? __expf(c[2] * sc) : 0.f;
            float e3 = (!need_mask || col + 1 <= trow1) ? __expf(c[3] * sc) : 0.f;
            rs0 += e0 + e1; rs1 += e2 + e3;
            *(float2*)&attn[((size_t)b * T_ + trow0) * T_ + col] = make_float2(e0, e1);
            *(float2*)&attn[((size_t)b * T_ + trow1) * T_ + col] = make_float2(e2, e3);
        }
        // reduce across the 4 tig lanes (same g)
        rs0 += __shfl_xor_sync(0xffffffffu, rs0, 1);
        rs0 += __shfl_xor_sync(0xffffffffu, rs0, 2);
        rs1 += __shfl_xor_sync(0xffffffffu, rs1, 1);
        rs1 += __shfl_xor_sync(0xffffffffu, rs1, 2);
        if (tig == 0) {
            atomicAdd(&g_rowsum[(size_t)b * T_ + trow0], rs0);
            atomicAdd(&g_rowsum[(size_t)b * T_ + trow1], rs1);
        }
    }
}

// ---------------------------------------------------------------------------
// Kernel 3: res += (attn/rowsum) @ V, split-K over 512-wide s-spans.
// Fuses normalization: loader scales E by 1/rowsum, writes fp32 back to gmem
// (each attn element owned by exactly one span-CTA), feeds tf32 to MMA.
// grid=(4 spans, 32 t desc, 8 b), block=128 (4 warps 2x2). Tile 64t x 64h.
// ---------------------------------------------------------------------------
#define AV_SMEM (64 * 68 * 4 + 64 * 72 * 4 + 64 * 4)   // 35904 B
__global__ __launch_bounds__(128, 5) void av_kernel(float* __restrict__ attn,
                                                    float* __restrict__ res) {
    const int sc   = blockIdx.x;
    const int t_t  = 31 - blockIdx.y;   // big tiles first
    const int b    = blockIdx.z;
    const int t0   = t_t * 64;
    if (sc * 512 > t0 + 63) return;

    extern __shared__ unsigned smu[];
    unsigned* As = smu;            // [64 t][68 s] tf32
    unsigned* Vs = smu + 64 * 68;  // [64 s][72 h] tf32
    float* sinv  = (float*)(smu + 64 * 68 + 64 * 72);

    const int tid = threadIdx.x;
    if (tid < 64) sinv[tid] = 1.f / g_rowsum[(size_t)b * T_ + t0 + tid];
    __syncthreads();

    const float* v = g_v + (size_t)b * T_ * H_;
    const int warp = tid >> 5;
    const int lane = tid & 31;
    const int g    = lane >> 2;
    const int tig  = lane & 3;
    const int wm   = warp >> 1;   // 0..1
    const int wn   = warp & 1;    // 0..1

    float acc[2][4][4] = {};

    #pragma unroll
    for (int c2 = 0; c2 < 8; c2++) {
        const int s0 = sc * 512 + c2 * 64;
        if (s0 > t0 + 63) break;

        #pragma unroll
        for (int it = 0; it < 8; it++) {
            int idx = tid + it * 128;          // 1024 float4 = 64 x 16
            int r = idx >> 4, c4 = idx & 15;
            float* ap = &attn[((size_t)b * T_ + t0 + r) * T_ + s0 + c4 * 4];
            float4 f = *(const float4*)ap;
            float iv = sinv[r];
            f = make_float4(f.x * iv, f.y * iv, f.z * iv, f.w * iv);
            *(float4*)ap = f;                  // normalized fp32 back to gmem
            *(uint4*)&As[r * 68 + c4 * 4] = tf32x4(f);
        }
        #pragma unroll
        for (int it = 0; it < 8; it++) {
            int idx = tid + it * 128;
            int r = idx >> 4, c4 = idx & 15;
            *(uint4*)&Vs[r * 72 + c4 * 4] =
                tf32x4(*(const float4*)&v[(size_t)(s0 + r) * H_ + c4 * 4]);
        }
        __syncthreads();

        #pragma unroll
        for (int k8 = 0; k8 < 8; k8++) {
            const int kb = k8 * 8;
            unsigned a[2][4];
            #pragma unroll
            for (int mi = 0; mi < 2; mi++) {
                int m0 = wm * 32 + mi * 16;
                a[mi][0] = As[(m0 + g) * 68 + kb + tig];
                a[mi][1] = As[(m0 + g + 8) * 68 + kb + tig];
                a[mi][2] = As[(m0 + g) * 68 + kb + tig + 4];
                a[mi][3] = As[(m0 + g + 8) * 68 + kb + tig + 4];
            }
            #pragma unroll
            for (int nj = 0; nj < 4; nj++) {
                int n0 = wn * 32 + nj * 8;
                unsigned bb[2];
                bb[0] = Vs[(kb + tig) * 72 + n0 + g];
                bb[1] = Vs[(kb + tig + 4) * 72 + n0 + g];
                #pragma unroll
                for (int mi = 0; mi < 2; mi++) mma8(acc[mi][nj], a[mi], bb);
            }
        }
        __syncthreads();
    }

    #pragma unroll
    for (int mi = 0; mi < 2; mi++) {
        #pragma unroll
        for (int nj = 0; nj < 4; nj++) {
            int m0 = t0 + wm * 32 + mi * 16;
            int n0 = wn * 32 + nj * 8 + tig * 2;
            float* c = acc[mi][nj];
            size_t r0 = ((size_t)b * T_ + m0 + g) * H_ + n0;
            size_t r1 = ((size_t)b * T_ + m0 + g + 8) * H_ + n0;
            atomicAdd(&res[r0],     c[0]);
            atomicAdd(&res[r0 + 1], c[1]);
            atomicAdd(&res[r1],     c[2]);
            atomicAdd(&res[r1 + 1], c[3]);
        }
    }
}

// ---------------------------------------------------------------------------
extern "C" void kernel_launch(void* const* d_in, const int* in_sizes, int n_in,
                              void* d_out, int out_size) {
    (void)in_sizes; (void)n_in;
    const float* x  = (const float*)d_in[0];
    const float* Wq = (const float*)d_in[1];
    const float* Wk = (const float*)d_in[2];
    const float* Wv = (const float*)d_in[3];

    const size_t n_res  = (size_t)B_ * T_ * H_;
    const size_t n_attn = (size_t)B_ * T_ * T_;

    float* attn_scratch = nullptr;
    float* res_scratch = nullptr;
    float* rowsum = nullptr;
    cudaGetSymbolAddress((void**)&attn_scratch, g_attn_scratch);
    cudaGetSymbolAddress((void**)&res_scratch, g_res);
    cudaGetSymbolAddress((void**)&rowsum, g_rowsum);

    float* res;
    float* attn;
    if ((size_t)out_size == n_res + n_attn) {
        res  = (float*)d_out;
        attn = (float*)d_out + n_res;
    } else if ((size_t)out_size == n_attn) {
        attn = (float*)d_out;
        res  = res_scratch;
    } else {
        res  = (float*)d_out;
        attn = attn_scratch;
    }

    cudaFuncSetAttribute(proj_kernel,   cudaFuncAttributeMaxDynamicSharedMemorySize, PROJ_SMEM);
    cudaFuncSetAttribute(scores_kernel, cudaFuncAttributeMaxDynamicSharedMemorySize, SCORES_SMEM);
    cudaFuncSetAttribute(av_kernel,     cudaFuncAttributeMaxDynamicSharedMemorySize, AV_SMEM);

    cudaMemsetAsync(rowsum, 0, NROWS * sizeof(float));
    cudaMemsetAsync(res, 0, n_res * sizeof(float));
    proj_kernel<<<dim3(128, 3), 256, PROJ_SMEM>>>(x, Wq, Wk, Wv);
    scores_kernel<<<dim3(16, 32, 8), 128, SCORES_SMEM>>>(attn);
    av_kernel<<<dim3(4, 32, 8), 128, AV_SMEM>>>(attn, res);
}